// round 4
// baseline (speedup 1.0000x reference)
#include <cuda_runtime.h>

// Jacobi 5-iteration temporally-blocked cross stencil, sm_103a.
// Vectorized smem (float4/float2), B=16, H=W=1024, radius-2 cross,
// boundary ring (width 2) frozen.

constexpr int HH  = 1024;
constexpr int WW  = 1024;
constexpr int NB  = 16;
constexpr int T   = 64;             // output tile
constexpr int RAD = 10;             // 2*5 halo
constexpr int L   = 84;             // T + 2*RAD
constexpr int LP  = 88;             // padded stride, multiple of 4
constexpr int NT  = 512;
constexpr int SMEM_BYTES = 3 * L * LP * 4;   // A, B, R -> 88,704 B

// ---- middle sweeps k=0..3: 4-aligned column groups, write to smem ----
template<int K, bool EDGE>
__device__ __forceinline__ void sweep(const float* __restrict__ cur,
                                      float* __restrict__ nxt,
                                      const float* __restrict__ R,
                                      int tid, int ti, int tj,
                                      float k1x, float k2x, float k1y, float k2y)
{
    constexpr int lo  = 2 + 2 * K;
    constexpr int hi  = L - lo;
    constexpr int cg0 = lo & ~3;                 // 4-aligned start col
    constexpr int cgE = (hi + 3) & ~3;           // 4-aligned end
    constexpr int ncg = (cgE - cg0) / 4;         // 21,19,19,17
    constexpr int total = (hi - lo) * ncg;

    for (int idx = tid; idx < total; idx += NT) {
        const int row = idx / ncg;               // div by compile-time const
        const int li  = lo + row;
        const int lj  = cg0 + 4 * (idx - row * ncg);
        const float* base = cur + li * LP + lj;

        const float4 vm2 = *(const float4*)(base - 2 * LP);
        const float4 vm1 = *(const float4*)(base - LP);
        const float4 vp1 = *(const float4*)(base + LP);
        const float4 vp2 = *(const float4*)(base + 2 * LP);
        const float2 hl  = *(const float2*)(base - 2);
        const float4 c0  = *(const float4*)(base);
        const float2 hr  = *(const float2*)(base + 4);
        const float4 rr  = *(const float4*)(R + li * LP + lj);

        // horizontal window h0..h7 = cols lj-2 .. lj+5
        const float h0 = hl.x, h1 = hl.y, h2 = c0.x, h3 = c0.y;
        const float h4 = c0.z, h5 = c0.w, h6 = hr.x, h7 = hr.y;

        float4 o;
        o.x = rr.x - (k2x * (vm2.x + vp2.x) + k1x * (vm1.x + vp1.x)
                    + k2y * (h0 + h4) + k1y * (h1 + h3));
        o.y = rr.y - (k2x * (vm2.y + vp2.y) + k1x * (vm1.y + vp1.y)
                    + k2y * (h1 + h5) + k1y * (h2 + h4));
        o.z = rr.z - (k2x * (vm2.z + vp2.z) + k1x * (vm1.z + vp1.z)
                    + k2y * (h2 + h6) + k1y * (h3 + h5));
        o.w = rr.w - (k2x * (vm2.w + vp2.w) + k1x * (vm1.w + vp1.w)
                    + k2y * (h3 + h7) + k1y * (h4 + h6));

        if (EDGE) {
            const int gi = ti + li - RAD;
            const int gj = tj + lj - RAD;
            const bool ir = (unsigned)(gi - 2) < (unsigned)(HH - 4);
            o.x = (ir && (unsigned)(gj + 0 - 2) < (unsigned)(WW - 4)) ? o.x : c0.x;
            o.y = (ir && (unsigned)(gj + 1 - 2) < (unsigned)(WW - 4)) ? o.y : c0.y;
            o.z = (ir && (unsigned)(gj + 2 - 2) < (unsigned)(WW - 4)) ? o.z : c0.z;
            o.w = (ir && (unsigned)(gj + 3 - 2) < (unsigned)(WW - 4)) ? o.w : c0.w;
        }
        *(float4*)(nxt + li * LP + lj) = o;
    }
}

// ---- final sweep k=4: columns at lj = 10 + 4m so the global store is
//      16B aligned (gj = tj + lj - 10 == 0 mod 4) -> STG.128 ----
template<bool EDGE>
__device__ __forceinline__ void sweep_last(const float* __restrict__ cur,
                                           const float* __restrict__ R,
                                           float* __restrict__ ob,
                                           int tid, int ti, int tj,
                                           float k1x, float k2x, float k1y, float k2y)
{
    constexpr int total = T * (T / 4);           // 64 rows x 16 groups
    for (int idx = tid; idx < total; idx += NT) {
        const int li = RAD + (idx >> 4);
        const int lj = RAD + 4 * (idx & 15);     // lj % 4 == 2
        const float* base = cur + li * LP + lj;

        // vertical: lj%4==2 -> 8B-aligned float2 pairs
        const float2 vm2a = *(const float2*)(base - 2 * LP);
        const float2 vm2b = *(const float2*)(base - 2 * LP + 2);
        const float2 vm1a = *(const float2*)(base - LP);
        const float2 vm1b = *(const float2*)(base - LP + 2);
        const float2 vp1a = *(const float2*)(base + LP);
        const float2 vp1b = *(const float2*)(base + LP + 2);
        const float2 vp2a = *(const float2*)(base + 2 * LP);
        const float2 vp2b = *(const float2*)(base + 2 * LP + 2);
        // horizontal: two aligned float4 at lj-2, lj+2 cover cols lj-2..lj+5
        const float4 ha = *(const float4*)(base - 2);
        const float4 hb = *(const float4*)(base + 2);
        const float2 ra = *(const float2*)(R + li * LP + lj);
        const float2 rb = *(const float2*)(R + li * LP + lj + 2);

        const float h0 = ha.x, h1 = ha.y, h2 = ha.z, h3 = ha.w;
        const float h4 = hb.x, h5 = hb.y, h6 = hb.z, h7 = hb.w;

        float4 o;
        o.x = ra.x - (k2x * (vm2a.x + vp2a.x) + k1x * (vm1a.x + vp1a.x)
                    + k2y * (h0 + h4) + k1y * (h1 + h3));
        o.y = ra.y - (k2x * (vm2a.y + vp2a.y) + k1x * (vm1a.y + vp1a.y)
                    + k2y * (h1 + h5) + k1y * (h2 + h4));
        o.z = rb.x - (k2x * (vm2b.x + vp2b.x) + k1x * (vm1b.x + vp1b.x)
                    + k2y * (h2 + h6) + k1y * (h3 + h5));
        o.w = rb.y - (k2x * (vm2b.y + vp2b.y) + k1x * (vm1b.y + vp1b.y)
                    + k2y * (h3 + h7) + k1y * (h4 + h6));

        const int gi = ti + li - RAD;
        const int gj = tj + lj - RAD;
        if (EDGE) {
            const bool ir = (unsigned)(gi - 2) < (unsigned)(HH - 4);
            o.x = (ir && (unsigned)(gj + 0 - 2) < (unsigned)(WW - 4)) ? o.x : h2;
            o.y = (ir && (unsigned)(gj + 1 - 2) < (unsigned)(WW - 4)) ? o.y : h3;
            o.z = (ir && (unsigned)(gj + 2 - 2) < (unsigned)(WW - 4)) ? o.z : h4;
            o.w = (ir && (unsigned)(gj + 3 - 2) < (unsigned)(WW - 4)) ? o.w : h5;
        }
        *(float4*)(ob + (size_t)gi * WW + gj) = o;
    }
}

template<bool EDGE>
__device__ __forceinline__ void run_all(float* A, float* Bf, const float* R,
                                        float* ob, int tid, int ti, int tj,
                                        float k1x, float k2x, float k1y, float k2y)
{
    sweep<0, EDGE>(A,  Bf, R, tid, ti, tj, k1x, k2x, k1y, k2y);
    __syncthreads();
    sweep<1, EDGE>(Bf, A,  R, tid, ti, tj, k1x, k2x, k1y, k2y);
    __syncthreads();
    sweep<2, EDGE>(A,  Bf, R, tid, ti, tj, k1x, k2x, k1y, k2y);
    __syncthreads();
    sweep<3, EDGE>(Bf, A,  R, tid, ti, tj, k1x, k2x, k1y, k2y);
    __syncthreads();
    sweep_last<EDGE>(A, R, ob, tid, ti, tj, k1x, k2x, k1y, k2y);
}

__global__ void __launch_bounds__(NT, 2)
jacobi5_fused(const float* __restrict__ g0,
              const float* __restrict__ rhs,
              const float* __restrict__ dx,
              float* __restrict__ out)
{
    extern __shared__ float sm[];
    float* A  = sm;                 // g buffer 0: L x LP
    float* Bf = sm + L * LP;        // g buffer 1
    float* R  = sm + 2 * L * LP;    // dinv-prescaled rhs, full local coords

    const int b  = blockIdx.z;
    const int ti = blockIdx.y * T;
    const int tj = blockIdx.x * T;

    const float ix = 1.0f / dx[2 * b + 0];
    const float iy = 1.0f / dx[2 * b + 1];
    const float sx = ix * ix;
    const float sy = iy * iy;
    const float dinv = 1.0f / (-2.5f * (sx + sy));
    const float k1x = dinv * sx * (4.0f / 3.0f);
    const float k2x = dinv * sx * (-1.0f / 12.0f);
    const float k1y = dinv * sy * (4.0f / 3.0f);
    const float k2y = dinv * sy * (-1.0f / 12.0f);

    const float* gb = g0  + (size_t)b * HH * WW;
    const float* rb = rhs + (size_t)b * HH * WW;
    float*       ob = out + (size_t)b * HH * WW;

    const int tid = threadIdx.x;
    const bool edge = (blockIdx.x == 0) | (blockIdx.x == gridDim.x - 1) |
                      (blockIdx.y == 0) | (blockIdx.y == gridDim.y - 1);

    if (edge) {
        for (int idx = tid; idx < L * L; idx += NT) {
            const int li = idx / L, lj = idx - (idx / L) * L;
            const int gi = ti + li - RAD, gj = tj + lj - RAD;
            float v = 0.0f;
            if (((unsigned)gi < (unsigned)HH) && ((unsigned)gj < (unsigned)WW))
                v = gb[(size_t)gi * WW + gj];
            A[li * LP + lj] = v;
        }
        for (int idx = tid; idx < L * L; idx += NT) {
            const int li = idx / L, lj = idx - (idx / L) * L;
            const int gi = ti + li - RAD, gj = tj + lj - RAD;
            float v = 0.0f;
            if (((unsigned)gi < (unsigned)HH) && ((unsigned)gj < (unsigned)WW))
                v = rb[(size_t)gi * WW + gj];
            R[li * LP + lj] = dinv * v;
        }
    } else {
        for (int idx = tid; idx < L * L; idx += NT) {
            const int li = idx / L, lj = idx - (idx / L) * L;
            const int gi = ti + li - RAD, gj = tj + lj - RAD;
            A[li * LP + lj] = gb[(size_t)gi * WW + gj];
        }
        for (int idx = tid; idx < L * L; idx += NT) {
            const int li = idx / L, lj = idx - (idx / L) * L;
            const int gi = ti + li - RAD, gj = tj + lj - RAD;
            R[li * LP + lj] = dinv * rb[(size_t)gi * WW + gj];
        }
    }
    __syncthreads();

    if (edge)
        run_all<true >(A, Bf, R, ob, tid, ti, tj, k1x, k2x, k1y, k2y);
    else
        run_all<false>(A, Bf, R, ob, tid, ti, tj, k1x, k2x, k1y, k2y);
}

extern "C" void kernel_launch(void* const* d_in, const int* in_sizes, int n_in,
                              void* d_out, int out_size) {
    const float* g0  = (const float*)d_in[0];
    const float* rhs = (const float*)d_in[1];
    const float* dx  = (const float*)d_in[2];
    float* out = (float*)d_out;

    cudaFuncSetAttribute(jacobi5_fused,
                         cudaFuncAttributeMaxDynamicSharedMemorySize, SMEM_BYTES);

    dim3 grid(WW / T, HH / T, NB);   // 16 x 16 x 16
    jacobi5_fused<<<grid, NT, SMEM_BYTES>>>(g0, rhs, dx, out);
}

// round 5
// speedup vs baseline: 1.1202x; 1.1202x over previous
#include <cuda_runtime.h>

// Jacobi 5-iteration temporally-blocked cross stencil, sm_103a.
// Vertical register rolling + vectorized smem. B=16, H=W=1024,
// radius-2 cross, boundary ring (width 2) frozen.

constexpr int HH  = 1024;
constexpr int WW  = 1024;
constexpr int NB  = 16;
constexpr int T   = 64;             // output tile
constexpr int RAD = 10;             // 2*5 halo
constexpr int L   = 84;             // T + 2*RAD
constexpr int LP  = 88;             // padded stride, multiple of 4
constexpr int NT  = 512;
constexpr int SMEM_BYTES = 3 * L * LP * 4;   // A, B, R -> 88,704 B

// ---- middle sweeps k=0..3: each thread computes a 4-col x 4-row block,
//      rolling a 5-row float4 register window down the rows. ----
template<int K, bool EDGE>
__device__ __forceinline__ void sweep(const float* __restrict__ cur,
                                      float* __restrict__ nxt,
                                      const float* __restrict__ R,
                                      int tid, int ti, int tj,
                                      float k1x, float k2x, float k1y, float k2y)
{
    constexpr int lo  = 2 + 2 * K;
    constexpr int hi  = L - lo;
    constexpr int w   = hi - lo;                 // rows: 80,76,72,68 (div by 4)
    constexpr int cg0 = lo & ~3;
    constexpr int cgE = (hi + 3) & ~3;
    constexpr int ncg = (cgE - cg0) / 4;         // col groups: 21,19,19,17
    constexpr int G   = 4;                       // rows per thread
    constexpr int nrb = w / G;                   // row blocks: 20,19,18,17

    if (tid >= ncg * nrb) return;
    const int rb = tid / ncg;                    // div by compile-time const
    const int cg = tid - rb * ncg;
    const int li0 = lo + rb * G;
    const int lj  = cg0 + 4 * cg;

    const float* base = cur + li0 * LP + lj;
    // preload rows li0-2 .. li0+1
    float4 w0 = *(const float4*)(base - 2 * LP);
    float4 w1 = *(const float4*)(base - LP);
    float4 w2 = *(const float4*)(base);
    float4 w3 = *(const float4*)(base + LP);

    #pragma unroll
    for (int g = 0; g < G; ++g) {
        const int li = li0 + g;
        const float4 w4 = *(const float4*)(base + (g + 2) * LP);
        const float2 hl = *(const float2*)(cur + li * LP + lj - 2);
        const float2 hr = *(const float2*)(cur + li * LP + lj + 4);
        const float4 rr = *(const float4*)(R + li * LP + lj);

        // horizontal window h0..h7 = cols lj-2 .. lj+5 (center row = w2)
        const float h0 = hl.x, h1 = hl.y, h2 = w2.x, h3 = w2.y;
        const float h4 = w2.z, h5 = w2.w, h6 = hr.x, h7 = hr.y;

        float4 o;
        o.x = rr.x - (k2x * (w0.x + w4.x) + k1x * (w1.x + w3.x)
                    + k2y * (h0 + h4) + k1y * (h1 + h3));
        o.y = rr.y - (k2x * (w0.y + w4.y) + k1x * (w1.y + w3.y)
                    + k2y * (h1 + h5) + k1y * (h2 + h4));
        o.z = rr.z - (k2x * (w0.z + w4.z) + k1x * (w1.z + w3.z)
                    + k2y * (h2 + h6) + k1y * (h3 + h5));
        o.w = rr.w - (k2x * (w0.w + w4.w) + k1x * (w1.w + w3.w)
                    + k2y * (h3 + h7) + k1y * (h4 + h6));

        if (EDGE) {
            const int gi = ti + li - RAD;
            const int gj = tj + lj - RAD;
            const bool ir = (unsigned)(gi - 2) < (unsigned)(HH - 4);
            o.x = (ir && (unsigned)(gj + 0 - 2) < (unsigned)(WW - 4)) ? o.x : w2.x;
            o.y = (ir && (unsigned)(gj + 1 - 2) < (unsigned)(WW - 4)) ? o.y : w2.y;
            o.z = (ir && (unsigned)(gj + 2 - 2) < (unsigned)(WW - 4)) ? o.z : w2.z;
            o.w = (ir && (unsigned)(gj + 3 - 2) < (unsigned)(WW - 4)) ? o.w : w2.w;
        }
        *(float4*)(nxt + li * LP + lj) = o;

        w0 = w1; w1 = w2; w2 = w3; w3 = w4;   // roll window
    }
}

// ---- final sweep k=4: columns at lj = 10 + 4m so the global store is
//      16B aligned (gj = tj + lj - 10 == 0 mod 4) -> STG.128 ----
template<bool EDGE>
__device__ __forceinline__ void sweep_last(const float* __restrict__ cur,
                                           const float* __restrict__ R,
                                           float* __restrict__ ob,
                                           int tid, int ti, int tj,
                                           float k1x, float k2x, float k1y, float k2y)
{
    constexpr int total = T * (T / 4);           // 64 rows x 16 groups
    #pragma unroll 2
    for (int idx = tid; idx < total; idx += NT) {
        const int li = RAD + (idx >> 4);
        const int lj = RAD + 4 * (idx & 15);     // lj % 4 == 2
        const float* base = cur + li * LP + lj;

        const float2 vm2a = *(const float2*)(base - 2 * LP);
        const float2 vm2b = *(const float2*)(base - 2 * LP + 2);
        const float2 vm1a = *(const float2*)(base - LP);
        const float2 vm1b = *(const float2*)(base - LP + 2);
        const float2 vp1a = *(const float2*)(base + LP);
        const float2 vp1b = *(const float2*)(base + LP + 2);
        const float2 vp2a = *(const float2*)(base + 2 * LP);
        const float2 vp2b = *(const float2*)(base + 2 * LP + 2);
        const float4 ha = *(const float4*)(base - 2);   // cols lj-2..lj+1
        const float4 hb = *(const float4*)(base + 2);   // cols lj+2..lj+5
        const float2 ra = *(const float2*)(R + li * LP + lj);
        const float2 rb = *(const float2*)(R + li * LP + lj + 2);

        const float h0 = ha.x, h1 = ha.y, h2 = ha.z, h3 = ha.w;
        const float h4 = hb.x, h5 = hb.y, h6 = hb.z, h7 = hb.w;

        float4 o;
        o.x = ra.x - (k2x * (vm2a.x + vp2a.x) + k1x * (vm1a.x + vp1a.x)
                    + k2y * (h0 + h4) + k1y * (h1 + h3));
        o.y = ra.y - (k2x * (vm2a.y + vp2a.y) + k1x * (vm1a.y + vp1a.y)
                    + k2y * (h1 + h5) + k1y * (h2 + h4));
        o.z = rb.x - (k2x * (vm2b.x + vp2b.x) + k1x * (vm1b.x + vp1b.x)
                    + k2y * (h2 + h6) + k1y * (h3 + h5));
        o.w = rb.y - (k2x * (vm2b.y + vp2b.y) + k1x * (vm1b.y + vp1b.y)
                    + k2y * (h3 + h7) + k1y * (h4 + h6));

        const int gi = ti + li - RAD;
        const int gj = tj + lj - RAD;
        if (EDGE) {
            const bool ir = (unsigned)(gi - 2) < (unsigned)(HH - 4);
            o.x = (ir && (unsigned)(gj + 0 - 2) < (unsigned)(WW - 4)) ? o.x : h2;
            o.y = (ir && (unsigned)(gj + 1 - 2) < (unsigned)(WW - 4)) ? o.y : h3;
            o.z = (ir && (unsigned)(gj + 2 - 2) < (unsigned)(WW - 4)) ? o.z : h4;
            o.w = (ir && (unsigned)(gj + 3 - 2) < (unsigned)(WW - 4)) ? o.w : h5;
        }
        *(float4*)(ob + (size_t)gi * WW + gj) = o;
    }
}

template<bool EDGE>
__device__ __forceinline__ void run_all(float* A, float* Bf, const float* R,
                                        float* ob, int tid, int ti, int tj,
                                        float k1x, float k2x, float k1y, float k2y)
{
    sweep<0, EDGE>(A,  Bf, R, tid, ti, tj, k1x, k2x, k1y, k2y);
    __syncthreads();
    sweep<1, EDGE>(Bf, A,  R, tid, ti, tj, k1x, k2x, k1y, k2y);
    __syncthreads();
    sweep<2, EDGE>(A,  Bf, R, tid, ti, tj, k1x, k2x, k1y, k2y);
    __syncthreads();
    sweep<3, EDGE>(Bf, A,  R, tid, ti, tj, k1x, k2x, k1y, k2y);
    __syncthreads();
    sweep_last<EDGE>(A, R, ob, tid, ti, tj, k1x, k2x, k1y, k2y);
}

__global__ void __launch_bounds__(NT, 2)
jacobi5_fused(const float* __restrict__ g0,
              const float* __restrict__ rhs,
              const float* __restrict__ dx,
              float* __restrict__ out)
{
    extern __shared__ float sm[];
    float* A  = sm;                 // g buffer 0: L x LP
    float* Bf = sm + L * LP;        // g buffer 1
    float* R  = sm + 2 * L * LP;    // dinv-prescaled rhs, full local coords

    const int b  = blockIdx.z;
    const int ti = blockIdx.y * T;
    const int tj = blockIdx.x * T;

    const float ix = 1.0f / dx[2 * b + 0];
    const float iy = 1.0f / dx[2 * b + 1];
    const float sx = ix * ix;
    const float sy = iy * iy;
    const float dinv = 1.0f / (-2.5f * (sx + sy));
    const float k1x = dinv * sx * (4.0f / 3.0f);
    const float k2x = dinv * sx * (-1.0f / 12.0f);
    const float k1y = dinv * sy * (4.0f / 3.0f);
    const float k2y = dinv * sy * (-1.0f / 12.0f);

    const float* gb = g0  + (size_t)b * HH * WW;
    const float* rb = rhs + (size_t)b * HH * WW;
    float*       ob = out + (size_t)b * HH * WW;

    const int tid = threadIdx.x;
    const bool edge = (blockIdx.x == 0) | (blockIdx.x == gridDim.x - 1) |
                      (blockIdx.y == 0) | (blockIdx.y == gridDim.y - 1);

    if (edge) {
        for (int idx = tid; idx < L * L; idx += NT) {
            const int li = idx / L, lj = idx - (idx / L) * L;
            const int gi = ti + li - RAD, gj = tj + lj - RAD;
            float v = 0.0f;
            if (((unsigned)gi < (unsigned)HH) && ((unsigned)gj < (unsigned)WW))
                v = gb[(size_t)gi * WW + gj];
            A[li * LP + lj] = v;
        }
        for (int idx = tid; idx < L * L; idx += NT) {
            const int li = idx / L, lj = idx - (idx / L) * L;
            const int gi = ti + li - RAD, gj = tj + lj - RAD;
            float v = 0.0f;
            if (((unsigned)gi < (unsigned)HH) && ((unsigned)gj < (unsigned)WW))
                v = rb[(size_t)gi * WW + gj];
            R[li * LP + lj] = dinv * v;
        }
    } else {
        for (int idx = tid; idx < L * L; idx += NT) {
            const int li = idx / L, lj = idx - (idx / L) * L;
            const int gi = ti + li - RAD, gj = tj + lj - RAD;
            A[li * LP + lj] = gb[(size_t)gi * WW + gj];
        }
        for (int idx = tid; idx < L * L; idx += NT) {
            const int li = idx / L, lj = idx - (idx / L) * L;
            const int gi = ti + li - RAD, gj = tj + lj - RAD;
            R[li * LP + lj] = dinv * rb[(size_t)gi * WW + gj];
        }
    }
    __syncthreads();

    if (edge)
        run_all<true >(A, Bf, R, ob, tid, ti, tj, k1x, k2x, k1y, k2y);
    else
        run_all<false>(A, Bf, R, ob, tid, ti, tj, k1x, k2x, k1y, k2y);
}

extern "C" void kernel_launch(void* const* d_in, const int* in_sizes, int n_in,
                              void* d_out, int out_size) {
    const float* g0  = (const float*)d_in[0];
    const float* rhs = (const float*)d_in[1];
    const float* dx  = (const float*)d_in[2];
    float* out = (float*)d_out;

    cudaFuncSetAttribute(jacobi5_fused,
                         cudaFuncAttributeMaxDynamicSharedMemorySize, SMEM_BYTES);

    dim3 grid(WW / T, HH / T, NB);   // 16 x 16 x 16
    jacobi5_fused<<<grid, NT, SMEM_BYTES>>>(g0, rhs, dx, out);
}

// round 6
// speedup vs baseline: 1.8969x; 1.6934x over previous
#include <cuda_runtime.h>

// Jacobi 5-iteration temporally-blocked cross stencil, sm_103a.
// 3 CTAs/SM: rhs streamed from L2 each sweep (no smem copy), uniform
// full-region sweeps, vertical register rolling, vectorized smem.
// B=16, H=W=1024, radius-2 cross, boundary ring (width 2) frozen.

constexpr int HH  = 1024;
constexpr int WW  = 1024;
constexpr int NB  = 16;
constexpr int T   = 64;             // output tile
constexpr int RAD = 10;             // 2*5 halo
constexpr int L   = 84;             // local extent
constexpr int LP  = 84;             // stride (mult of 4; 21 banks -> conflict free)
constexpr int NT  = 512;
// +2-word shift so columns lj = 2+4m land on 16B boundaries; L*LP is mult of 4
constexpr int SMEM_BYTES = (2 * L * LP + 4) * 4;   // 56,480 B -> 3 CTAs/SM

// ---- middle sweeps: full region rows/cols [2,82), 20x20 4x4 blocks ----
template<bool EDGE>
__device__ __forceinline__ void sweep_mid(const float* __restrict__ cur,
                                          float* __restrict__ nxt,
                                          const float* __restrict__ rg,
                                          int tid, int ti, int tj, float dinv,
                                          float k1x, float k2x, float k1y, float k2y)
{
    if (tid >= 400) return;
    const int rbk = tid / 20;
    const int cg  = tid - rbk * 20;
    const int li0 = 2 + 4 * rbk;
    const int lj  = 2 + 4 * cg;
    const int gj  = tj + lj - RAD;          // 4-aligned

    const float* base = cur + li0 * LP + lj;
    float4 w0 = *(const float4*)(base - 2 * LP);
    float4 w1 = *(const float4*)(base - LP);
    float4 w2 = *(const float4*)(base);
    float4 w3 = *(const float4*)(base + LP);

    #pragma unroll
    for (int g = 0; g < 4; ++g) {
        const int li = li0 + g;
        const int gi = ti + li - RAD;
        const float4 w4 = *(const float4*)(base + (g + 2) * LP);
        const float2 hl = *(const float2*)(cur + li * LP + lj - 2);
        const float2 hr = *(const float2*)(cur + li * LP + lj + 4);
        float4 rr;
        if (EDGE) {
            // gj is 4-aligned and < WW implies gj+3 < WW; unsigned compare kills gi<0
            const bool ok = ((unsigned)gi < (unsigned)HH) && ((unsigned)gj < (unsigned)WW);
            rr = ok ? *(const float4*)(rg + (size_t)gi * WW + gj)
                    : make_float4(0.f, 0.f, 0.f, 0.f);
        } else {
            rr = *(const float4*)(rg + (size_t)gi * WW + gj);
        }

        const float h0 = hl.x, h1 = hl.y, h2 = w2.x, h3 = w2.y;
        const float h4 = w2.z, h5 = w2.w, h6 = hr.x, h7 = hr.y;

        float4 o;
        o.x = fmaf(rr.x, dinv, -(k2x * (w0.x + w4.x) + k1x * (w1.x + w3.x)
                               + k2y * (h0 + h4) + k1y * (h1 + h3)));
        o.y = fmaf(rr.y, dinv, -(k2x * (w0.y + w4.y) + k1x * (w1.y + w3.y)
                               + k2y * (h1 + h5) + k1y * (h2 + h4)));
        o.z = fmaf(rr.z, dinv, -(k2x * (w0.z + w4.z) + k1x * (w1.z + w3.z)
                               + k2y * (h2 + h6) + k1y * (h3 + h5)));
        o.w = fmaf(rr.w, dinv, -(k2x * (w0.w + w4.w) + k1x * (w1.w + w3.w)
                               + k2y * (h3 + h7) + k1y * (h4 + h6)));

        if (EDGE) {
            const bool ir = (unsigned)(gi - 2) < (unsigned)(HH - 4);
            o.x = (ir && (unsigned)(gj + 0 - 2) < (unsigned)(WW - 4)) ? o.x : w2.x;
            o.y = (ir && (unsigned)(gj + 1 - 2) < (unsigned)(WW - 4)) ? o.y : w2.y;
            o.z = (ir && (unsigned)(gj + 2 - 2) < (unsigned)(WW - 4)) ? o.z : w2.z;
            o.w = (ir && (unsigned)(gj + 3 - 2) < (unsigned)(WW - 4)) ? o.w : w2.w;
        }
        *(float4*)(nxt + li * LP + lj) = o;

        w0 = w1; w1 = w2; w2 = w3; w3 = w4;
    }
}

// ---- final sweep: output region [10,74)^2, 16x32 blocks of 4x2,
//      512 items == 512 threads, aligned STG.128 to global ----
template<bool EDGE>
__device__ __forceinline__ void sweep_last(const float* __restrict__ cur,
                                           const float* __restrict__ rg,
                                           float* __restrict__ ob,
                                           int tid, int ti, int tj, float dinv,
                                           float k1x, float k2x, float k1y, float k2y)
{
    const int rbk = tid >> 4;               // 0..31
    const int cg  = tid & 15;               // 0..15
    const int li0 = RAD + 2 * rbk;
    const int lj  = RAD + 4 * cg;
    const int gj  = tj + lj - RAD;          // in [tj, tj+64), always in image

    const float* base = cur + li0 * LP + lj;
    float4 w0 = *(const float4*)(base - 2 * LP);
    float4 w1 = *(const float4*)(base - LP);
    float4 w2 = *(const float4*)(base);
    float4 w3 = *(const float4*)(base + LP);

    #pragma unroll
    for (int g = 0; g < 2; ++g) {
        const int li = li0 + g;
        const int gi = ti + li - RAD;       // in [ti, ti+64), always in image
        const float4 w4 = *(const float4*)(base + (g + 2) * LP);
        const float2 hl = *(const float2*)(cur + li * LP + lj - 2);
        const float2 hr = *(const float2*)(cur + li * LP + lj + 4);
        const float4 rr = *(const float4*)(rg + (size_t)gi * WW + gj);

        const float h0 = hl.x, h1 = hl.y, h2 = w2.x, h3 = w2.y;
        const float h4 = w2.z, h5 = w2.w, h6 = hr.x, h7 = hr.y;

        float4 o;
        o.x = fmaf(rr.x, dinv, -(k2x * (w0.x + w4.x) + k1x * (w1.x + w3.x)
                               + k2y * (h0 + h4) + k1y * (h1 + h3)));
        o.y = fmaf(rr.y, dinv, -(k2x * (w0.y + w4.y) + k1x * (w1.y + w3.y)
                               + k2y * (h1 + h5) + k1y * (h2 + h4)));
        o.z = fmaf(rr.z, dinv, -(k2x * (w0.z + w4.z) + k1x * (w1.z + w3.z)
                               + k2y * (h2 + h6) + k1y * (h3 + h5)));
        o.w = fmaf(rr.w, dinv, -(k2x * (w0.w + w4.w) + k1x * (w1.w + w3.w)
                               + k2y * (h3 + h7) + k1y * (h4 + h6)));

        if (EDGE) {
            const bool ir = (unsigned)(gi - 2) < (unsigned)(HH - 4);
            o.x = (ir && (unsigned)(gj + 0 - 2) < (unsigned)(WW - 4)) ? o.x : w2.x;
            o.y = (ir && (unsigned)(gj + 1 - 2) < (unsigned)(WW - 4)) ? o.y : w2.y;
            o.z = (ir && (unsigned)(gj + 2 - 2) < (unsigned)(WW - 4)) ? o.z : w2.z;
            o.w = (ir && (unsigned)(gj + 3 - 2) < (unsigned)(WW - 4)) ? o.w : w2.w;
        }
        *(float4*)(ob + (size_t)gi * WW + gj) = o;

        w0 = w1; w1 = w2; w2 = w3; w3 = w4;
    }
}

template<bool EDGE>
__device__ __forceinline__ void run_all(float* A, float* Bf, const float* rg,
                                        float* ob, int tid, int ti, int tj, float dinv,
                                        float k1x, float k2x, float k1y, float k2y)
{
    sweep_mid<EDGE>(A,  Bf, rg, tid, ti, tj, dinv, k1x, k2x, k1y, k2y);
    __syncthreads();
    sweep_mid<EDGE>(Bf, A,  rg, tid, ti, tj, dinv, k1x, k2x, k1y, k2y);
    __syncthreads();
    sweep_mid<EDGE>(A,  Bf, rg, tid, ti, tj, dinv, k1x, k2x, k1y, k2y);
    __syncthreads();
    sweep_mid<EDGE>(Bf, A,  rg, tid, ti, tj, dinv, k1x, k2x, k1y, k2y);
    __syncthreads();
    sweep_last<EDGE>(A, rg, ob, tid, ti, tj, dinv, k1x, k2x, k1y, k2y);
}

__global__ void __launch_bounds__(NT, 3)
jacobi5_fused(const float* __restrict__ g0,
              const float* __restrict__ rhs,
              const float* __restrict__ dx,
              float* __restrict__ out)
{
    extern __shared__ float sm[];
    float* A  = sm + 2;             // +2-word shift: cols lj=2+4m are 16B aligned
    float* Bf = sm + 2 + L * LP;    // L*LP mult of 4 -> same alignment class

    const int b  = blockIdx.z;
    const int ti = blockIdx.y * T;
    const int tj = blockIdx.x * T;

    const float ix = 1.0f / dx[2 * b + 0];
    const float iy = 1.0f / dx[2 * b + 1];
    const float sx = ix * ix;
    const float sy = iy * iy;
    const float dinv = 1.0f / (-2.5f * (sx + sy));
    const float k1x = dinv * sx * (4.0f / 3.0f);
    const float k2x = dinv * sx * (-1.0f / 12.0f);
    const float k1y = dinv * sy * (4.0f / 3.0f);
    const float k2y = dinv * sy * (-1.0f / 12.0f);

    const float* gb = g0  + (size_t)b * HH * WW;
    const float* rg = rhs + (size_t)b * HH * WW;
    float*       ob = out + (size_t)b * HH * WW;

    const int tid = threadIdx.x;
    const bool edge = (blockIdx.x == 0) | (blockIdx.x == gridDim.x - 1) |
                      (blockIdx.y == 0) | (blockIdx.y == gridDim.y - 1);

    // ---- load g halo into A ----
    if (edge) {
        for (int idx = tid; idx < L * L; idx += NT) {
            const int li = idx / L, lj = idx - (idx / L) * L;
            const int gi = ti + li - RAD, gj = tj + lj - RAD;
            float v = 0.0f;
            if (((unsigned)gi < (unsigned)HH) && ((unsigned)gj < (unsigned)WW))
                v = gb[(size_t)gi * WW + gj];
            A[li * LP + lj] = v;
        }
    } else {
        for (int idx = tid; idx < L * L; idx += NT) {
            const int li = idx / L, lj = idx - (idx / L) * L;
            const int gi = ti + li - RAD, gj = tj + lj - RAD;
            A[li * LP + lj] = gb[(size_t)gi * WW + gj];
        }
    }
    __syncthreads();

    if (edge)
        run_all<true >(A, Bf, rg, ob, tid, ti, tj, dinv, k1x, k2x, k1y, k2y);
    else
        run_all<false>(A, Bf, rg, ob, tid, ti, tj, dinv, k1x, k2x, k1y, k2y);
}

extern "C" void kernel_launch(void* const* d_in, const int* in_sizes, int n_in,
                              void* d_out, int out_size) {
    const float* g0  = (const float*)d_in[0];
    const float* rhs = (const float*)d_in[1];
    const float* dx  = (const float*)d_in[2];
    float* out = (float*)d_out;

    cudaFuncSetAttribute(jacobi5_fused,
                         cudaFuncAttributeMaxDynamicSharedMemorySize, SMEM_BYTES);

    dim3 grid(WW / T, HH / T, NB);   // 16 x 16 x 16
    jacobi5_fused<<<grid, NT, SMEM_BYTES>>>(g0, rhs, dx, out);
}

// round 7
// speedup vs baseline: 2.0707x; 1.0916x over previous
#include <cuda_runtime.h>

// Jacobi 5-iteration temporally-blocked cross stencil, sm_103a.
// 3 CTAs/SM, rhs streamed from L2 with depth-2 software pipeline,
// uniform full-region sweeps, vertical register rolling, vectorized smem.
// B=16, H=W=1024, radius-2 cross, boundary ring (width 2) frozen.

constexpr int HH  = 1024;
constexpr int WW  = 1024;
constexpr int NB  = 16;
constexpr int T   = 64;             // output tile
constexpr int RAD = 10;             // 2*5 halo
constexpr int L   = 84;             // local extent
constexpr int LP  = 84;             // stride
constexpr int NT  = 512;
constexpr int SMEM_BYTES = (2 * L * LP + 4) * 4;   // 56,480 B -> 3 CTAs/SM

template<bool EDGE>
__device__ __forceinline__ float4 rr_load(const float* __restrict__ rg,
                                          int gi, int gj)
{
    if (EDGE) {
        const bool ok = ((unsigned)gi < (unsigned)HH) && ((unsigned)gj < (unsigned)WW);
        return ok ? *(const float4*)(rg + (size_t)gi * WW + gj)
                  : make_float4(0.f, 0.f, 0.f, 0.f);
    }
    return *(const float4*)(rg + (size_t)gi * WW + gj);
}

// ---- middle sweeps: full region rows/cols [2,82), 20x20 blocks of 4x4 ----
template<bool EDGE>
__device__ __forceinline__ void sweep_mid(const float* __restrict__ cur,
                                          float* __restrict__ nxt,
                                          const float* __restrict__ rg,
                                          int tid, int ti, int tj, float dinv,
                                          float k1x, float k2x, float k1y, float k2y)
{
    if (tid >= 400) return;
    const int rbk = tid / 20;
    const int cg  = tid - rbk * 20;
    const int li0 = 2 + 4 * rbk;
    const int lj  = 2 + 4 * cg;
    const int gi0 = ti + li0 - RAD;
    const int gj  = tj + lj - RAD;          // 4-aligned

    // depth-2 rhs pipeline: rows 0,1 in flight before the LDS chain starts
    float4 rrA = rr_load<EDGE>(rg, gi0 + 0, gj);
    float4 rrB = rr_load<EDGE>(rg, gi0 + 1, gj);

    const float* base = cur + li0 * LP + lj;
    float4 w0 = *(const float4*)(base - 2 * LP);
    float4 w1 = *(const float4*)(base - LP);
    float4 w2 = *(const float4*)(base);
    float4 w3 = *(const float4*)(base + LP);

    #pragma unroll
    for (int g = 0; g < 4; ++g) {
        const int li = li0 + g;
        const int gi = gi0 + g;
        const float4 w4 = *(const float4*)(base + (g + 2) * LP);
        const float2 hl = *(const float2*)(cur + li * LP + lj - 2);
        const float2 hr = *(const float2*)(cur + li * LP + lj + 4);

        const float4 rr = (g & 1) ? rrB : rrA;
        if (g == 0) rrA = rr_load<EDGE>(rg, gi0 + 2, gj);
        if (g == 1) rrB = rr_load<EDGE>(rg, gi0 + 3, gj);

        const float h0 = hl.x, h1 = hl.y, h2 = w2.x, h3 = w2.y;
        const float h4 = w2.z, h5 = w2.w, h6 = hr.x, h7 = hr.y;

        float4 o;
        o.x = fmaf(rr.x, dinv, -(k2x * (w0.x + w4.x) + k1x * (w1.x + w3.x)
                               + k2y * (h0 + h4) + k1y * (h1 + h3)));
        o.y = fmaf(rr.y, dinv, -(k2x * (w0.y + w4.y) + k1x * (w1.y + w3.y)
                               + k2y * (h1 + h5) + k1y * (h2 + h4)));
        o.z = fmaf(rr.z, dinv, -(k2x * (w0.z + w4.z) + k1x * (w1.z + w3.z)
                               + k2y * (h2 + h6) + k1y * (h3 + h5)));
        o.w = fmaf(rr.w, dinv, -(k2x * (w0.w + w4.w) + k1x * (w1.w + w3.w)
                               + k2y * (h3 + h7) + k1y * (h4 + h6)));

        if (EDGE) {
            const bool ir = (unsigned)(gi - 2) < (unsigned)(HH - 4);
            o.x = (ir && (unsigned)(gj + 0 - 2) < (unsigned)(WW - 4)) ? o.x : w2.x;
            o.y = (ir && (unsigned)(gj + 1 - 2) < (unsigned)(WW - 4)) ? o.y : w2.y;
            o.z = (ir && (unsigned)(gj + 2 - 2) < (unsigned)(WW - 4)) ? o.z : w2.z;
            o.w = (ir && (unsigned)(gj + 3 - 2) < (unsigned)(WW - 4)) ? o.w : w2.w;
        }
        *(float4*)(nxt + li * LP + lj) = o;

        w0 = w1; w1 = w2; w2 = w3; w3 = w4;
    }
}

// ---- final sweep: output region [10,74)^2, 32x16 blocks of 2x4,
//      512 items == 512 threads, aligned STG.128 to global ----
template<bool EDGE>
__device__ __forceinline__ void sweep_last(const float* __restrict__ cur,
                                           const float* __restrict__ rg,
                                           float* __restrict__ ob,
                                           int tid, int ti, int tj, float dinv,
                                           float k1x, float k2x, float k1y, float k2y)
{
    const int rbk = tid >> 4;               // 0..31
    const int cg  = tid & 15;               // 0..15
    const int li0 = RAD + 2 * rbk;
    const int lj  = RAD + 4 * cg;
    const int gi0 = ti + li0 - RAD;
    const int gj  = tj + lj - RAD;          // in [tj, tj+64): always in image

    float4 rrA = *(const float4*)(rg + (size_t)(gi0 + 0) * WW + gj);
    float4 rrB = *(const float4*)(rg + (size_t)(gi0 + 1) * WW + gj);

    const float* base = cur + li0 * LP + lj;
    float4 w0 = *(const float4*)(base - 2 * LP);
    float4 w1 = *(const float4*)(base - LP);
    float4 w2 = *(const float4*)(base);
    float4 w3 = *(const float4*)(base + LP);

    #pragma unroll
    for (int g = 0; g < 2; ++g) {
        const int li = li0 + g;
        const int gi = gi0 + g;
        const float4 w4 = *(const float4*)(base + (g + 2) * LP);
        const float2 hl = *(const float2*)(cur + li * LP + lj - 2);
        const float2 hr = *(const float2*)(cur + li * LP + lj + 4);
        const float4 rr = (g & 1) ? rrB : rrA;

        const float h0 = hl.x, h1 = hl.y, h2 = w2.x, h3 = w2.y;
        const float h4 = w2.z, h5 = w2.w, h6 = hr.x, h7 = hr.y;

        float4 o;
        o.x = fmaf(rr.x, dinv, -(k2x * (w0.x + w4.x) + k1x * (w1.x + w3.x)
                               + k2y * (h0 + h4) + k1y * (h1 + h3)));
        o.y = fmaf(rr.y, dinv, -(k2x * (w0.y + w4.y) + k1x * (w1.y + w3.y)
                               + k2y * (h1 + h5) + k1y * (h2 + h4)));
        o.z = fmaf(rr.z, dinv, -(k2x * (w0.z + w4.z) + k1x * (w1.z + w3.z)
                               + k2y * (h2 + h6) + k1y * (h3 + h5)));
        o.w = fmaf(rr.w, dinv, -(k2x * (w0.w + w4.w) + k1x * (w1.w + w3.w)
                               + k2y * (h3 + h7) + k1y * (h4 + h6)));

        if (EDGE) {
            const bool ir = (unsigned)(gi - 2) < (unsigned)(HH - 4);
            o.x = (ir && (unsigned)(gj + 0 - 2) < (unsigned)(WW - 4)) ? o.x : w2.x;
            o.y = (ir && (unsigned)(gj + 1 - 2) < (unsigned)(WW - 4)) ? o.y : w2.y;
            o.z = (ir && (unsigned)(gj + 2 - 2) < (unsigned)(WW - 4)) ? o.z : w2.z;
            o.w = (ir && (unsigned)(gj + 3 - 2) < (unsigned)(WW - 4)) ? o.w : w2.w;
        }
        *(float4*)(ob + (size_t)gi * WW + gj) = o;

        w0 = w1; w1 = w2; w2 = w3; w3 = w4;
    }
}

template<bool EDGE>
__device__ __forceinline__ void run_all(float* A, float* Bf, const float* rg,
                                        float* ob, int tid, int ti, int tj, float dinv,
                                        float k1x, float k2x, float k1y, float k2y)
{
    sweep_mid<EDGE>(A,  Bf, rg, tid, ti, tj, dinv, k1x, k2x, k1y, k2y);
    __syncthreads();
    sweep_mid<EDGE>(Bf, A,  rg, tid, ti, tj, dinv, k1x, k2x, k1y, k2y);
    __syncthreads();
    sweep_mid<EDGE>(A,  Bf, rg, tid, ti, tj, dinv, k1x, k2x, k1y, k2y);
    __syncthreads();
    sweep_mid<EDGE>(Bf, A,  rg, tid, ti, tj, dinv, k1x, k2x, k1y, k2y);
    __syncthreads();
    sweep_last<EDGE>(A, rg, ob, tid, ti, tj, dinv, k1x, k2x, k1y, k2y);
}

__global__ void __launch_bounds__(NT, 3)
jacobi5_fused(const float* __restrict__ g0,
              const float* __restrict__ rhs,
              const float* __restrict__ dx,
              float* __restrict__ out)
{
    extern __shared__ float sm[];
    float* A  = sm + 2;             // +2-word shift: cols lj=2+4m are 16B aligned
    float* Bf = sm + 2 + L * LP;

    const int b  = blockIdx.z;
    const int ti = blockIdx.y * T;
    const int tj = blockIdx.x * T;

    const float ix = 1.0f / dx[2 * b + 0];
    const float iy = 1.0f / dx[2 * b + 1];
    const float sx = ix * ix;
    const float sy = iy * iy;
    const float dinv = 1.0f / (-2.5f * (sx + sy));
    const float k1x = dinv * sx * (4.0f / 3.0f);
    const float k2x = dinv * sx * (-1.0f / 12.0f);
    const float k1y = dinv * sy * (4.0f / 3.0f);
    const float k2y = dinv * sy * (-1.0f / 12.0f);

    const float* gb = g0  + (size_t)b * HH * WW;
    const float* rg = rhs + (size_t)b * HH * WW;
    float*       ob = out + (size_t)b * HH * WW;

    const int tid = threadIdx.x;
    const bool edge = (blockIdx.x == 0) | (blockIdx.x == gridDim.x - 1) |
                      (blockIdx.y == 0) | (blockIdx.y == gridDim.y - 1);

    // ---- load g halo into A ----
    if (edge) {
        for (int idx = tid; idx < L * L; idx += NT) {
            const int li = idx / L, lj = idx - (idx / L) * L;
            const int gi = ti + li - RAD, gj = tj + lj - RAD;
            float v = 0.0f;
            if (((unsigned)gi < (unsigned)HH) && ((unsigned)gj < (unsigned)WW))
                v = gb[(size_t)gi * WW + gj];
            A[li * LP + lj] = v;
        }
    } else {
        // float2-vectorized: 84 rows x 42 groups; gj even -> 8B aligned both sides
        constexpr int NGB = L / 2;                    // 42
        for (int idx = tid; idx < L * NGB; idx += NT) {
            const int li = idx / NGB, m = idx - (idx / NGB) * NGB;
            const int lj = 2 * m;
            const int gi = ti + li - RAD, gj = tj + lj - RAD;
            const float2 v = *(const float2*)(gb + (size_t)gi * WW + gj);
            *(float2*)(A + li * LP + lj) = v;
        }
    }
    __syncthreads();

    if (edge)
        run_all<true >(A, Bf, rg, ob, tid, ti, tj, dinv, k1x, k2x, k1y, k2y);
    else
        run_all<false>(A, Bf, rg, ob, tid, ti, tj, dinv, k1x, k2x, k1y, k2y);
}

extern "C" void kernel_launch(void* const* d_in, const int* in_sizes, int n_in,
                              void* d_out, int out_size) {
    const float* g0  = (const float*)d_in[0];
    const float* rhs = (const float*)d_in[1];
    const float* dx  = (const float*)d_in[2];
    float* out = (float*)d_out;

    cudaFuncSetAttribute(jacobi5_fused,
                         cudaFuncAttributeMaxDynamicSharedMemorySize, SMEM_BYTES);

    dim3 grid(WW / T, HH / T, NB);   // 16 x 16 x 16
    jacobi5_fused<<<grid, NT, SMEM_BYTES>>>(g0, rhs, dx, out);
}